// round 1
// baseline (speedup 1.0000x reference)
#include <cuda_runtime.h>
#include <cstdint>

#define N_SRC 50000
#define N_DST 50000
#define IN_FEAT 128
#define OUT_FEAT 128

// Device-global scratch (allocation-free).
__device__ float g_neigh[(size_t)N_DST * IN_FEAT];
__device__ float g_deg[N_DST];

// ---------------------------------------------------------------------------
// Kernel 1: zero the accumulators
// ---------------------------------------------------------------------------
__global__ void zero_kernel() {
    const size_t total = (size_t)N_DST * IN_FEAT;
    size_t i = (size_t)blockIdx.x * blockDim.x + threadIdx.x;
    size_t stride = (size_t)gridDim.x * blockDim.x;
    // vectorized zero of g_neigh
    float4* p = reinterpret_cast<float4*>(g_neigh);
    size_t n4 = total / 4;
    for (size_t j = i; j < n4; j += stride)
        p[j] = make_float4(0.f, 0.f, 0.f, 0.f);
    for (size_t j = i; j < N_DST; j += stride)
        g_deg[j] = 0.f;
}

// ---------------------------------------------------------------------------
// Kernel 2: edge aggregation. One warp per edge.
//   Each lane loads one float4 (16B) of h_s[src] (512B row total) and does a
//   no-return vector reduction into g_neigh[dst].
// ---------------------------------------------------------------------------
__global__ __launch_bounds__(256) void edge_kernel(
    const float* __restrict__ h_s,
    const int* __restrict__ src,
    const int* __restrict__ dst,
    int n_edges)
{
    int warp = (blockIdx.x * blockDim.x + threadIdx.x) >> 5;
    int lane = threadIdx.x & 31;
    if (warp >= n_edges) return;

    int s = __ldg(src + warp);
    int d = __ldg(dst + warp);

    const float4 v = __ldg(reinterpret_cast<const float4*>(h_s + (size_t)s * IN_FEAT) + lane);
    float* p = g_neigh + (size_t)d * IN_FEAT + lane * 4;
    asm volatile("red.global.add.v4.f32 [%0], {%1, %2, %3, %4};"
                 :: "l"(p), "f"(v.x), "f"(v.y), "f"(v.z), "f"(v.w)
                 : "memory");
    if (lane == 0) atomicAdd(g_deg + d, 1.0f);
}

// ---------------------------------------------------------------------------
// Kernel 3: fused mean + concat + Linear.
//   out[d, o] = b[o] + sum_k h_d[d,k]*W[o,k] + (neigh[d,k]/max(deg,1))*W[o,128+k]
//   Classic 128x128 block tile, BK=16, 8x8 per-thread micro-tile, 256 threads.
// ---------------------------------------------------------------------------
#define BM 128
#define BN 128
#define BK 16

__global__ __launch_bounds__(256) void gemm_kernel(
    const float* __restrict__ h_d,
    const float* __restrict__ W,     // [128, 256] row-major
    const float* __restrict__ bias,  // [128]
    float* __restrict__ out)         // [N_DST, 128]
{
    __shared__ float As[BK][BM];
    __shared__ float Bs[BK][BN];
    __shared__ float sInv[BM];

    const int t  = threadIdx.x;
    const int bm = blockIdx.x * BM;
    const int tx = t & 15;   // 0..15 -> output cols (8 each)
    const int ty = t >> 4;   // 0..15 -> rows (8 each)

    // inverse degree per row of this block
    if (t < BM) {
        int r = bm + t;
        float dg = (r < N_DST) ? g_deg[r] : 1.0f;
        sInv[t] = 1.0f / fmaxf(dg, 1.0f);
    }

    float acc[8][8];
    #pragma unroll
    for (int i = 0; i < 8; ++i)
        #pragma unroll
        for (int j = 0; j < 8; ++j) acc[i][j] = 0.f;

    // phase 0: A = h_d, W columns [0,128)
    // phase 1: A = g_neigh * inv_deg, W columns [128,256)
    #pragma unroll 1
    for (int ph = 0; ph < 2; ++ph) {
        const float* __restrict__ A = ph ? g_neigh : h_d;
        #pragma unroll 1
        for (int k0 = 0; k0 < IN_FEAT; k0 += BK) {
            __syncthreads();
            // --- load A tile: 128 rows x 16 cols, transposed into As[k][m]
            #pragma unroll
            for (int i = 0; i < 2; ++i) {
                int idx = t + i * 256;          // 0..511
                int row = idx >> 2;             // 0..127
                int c4  = (idx & 3) * 4;        // 0,4,8,12
                int gr  = bm + row;
                float4 v = make_float4(0.f, 0.f, 0.f, 0.f);
                if (gr < N_DST)
                    v = __ldg(reinterpret_cast<const float4*>(A + (size_t)gr * IN_FEAT + k0 + c4));
                float s = ph ? sInv[row] : 1.0f;
                As[c4 + 0][row] = v.x * s;
                As[c4 + 1][row] = v.y * s;
                As[c4 + 2][row] = v.z * s;
                As[c4 + 3][row] = v.w * s;
            }
            // --- load B tile: Bs[k][o] = W[o][ph*128 + k0 + k]
            #pragma unroll
            for (int i = 0; i < 2; ++i) {
                int idx = t + i * 256;
                int o   = idx >> 2;
                int c4  = (idx & 3) * 4;
                float4 v = __ldg(reinterpret_cast<const float4*>(
                    W + (size_t)o * (2 * IN_FEAT) + ph * IN_FEAT + k0 + c4));
                Bs[c4 + 0][o] = v.x;
                Bs[c4 + 1][o] = v.y;
                Bs[c4 + 2][o] = v.z;
                Bs[c4 + 3][o] = v.w;
            }
            __syncthreads();
            // --- compute
            #pragma unroll
            for (int k = 0; k < BK; ++k) {
                float a[8], bb[8];
                #pragma unroll
                for (int i = 0; i < 8; ++i) a[i]  = As[k][ty * 8 + i];
                #pragma unroll
                for (int j = 0; j < 8; ++j) bb[j] = Bs[k][tx * 8 + j];
                #pragma unroll
                for (int i = 0; i < 8; ++i)
                    #pragma unroll
                    for (int j = 0; j < 8; ++j)
                        acc[i][j] += a[i] * bb[j];
            }
        }
    }

    // epilogue: add bias, store
    float bb[8];
    #pragma unroll
    for (int j = 0; j < 8; ++j) bb[j] = __ldg(bias + tx * 8 + j);

    #pragma unroll
    for (int i = 0; i < 8; ++i) {
        int r = bm + ty * 8 + i;
        if (r < N_DST) {
            float* orow = out + (size_t)r * OUT_FEAT + tx * 8;
            float4 v0 = make_float4(acc[i][0] + bb[0], acc[i][1] + bb[1],
                                    acc[i][2] + bb[2], acc[i][3] + bb[3]);
            float4 v1 = make_float4(acc[i][4] + bb[4], acc[i][5] + bb[5],
                                    acc[i][6] + bb[6], acc[i][7] + bb[7]);
            reinterpret_cast<float4*>(orow)[0] = v0;
            reinterpret_cast<float4*>(orow)[1] = v1;
        }
    }
}

// ---------------------------------------------------------------------------
extern "C" void kernel_launch(void* const* d_in, const int* in_sizes, int n_in,
                              void* d_out, int out_size)
{
    const float* h_s = (const float*)d_in[0];
    const float* h_d = (const float*)d_in[1];
    const int*   src = (const int*)d_in[2];
    const int*   dst = (const int*)d_in[3];
    const float* W   = (const float*)d_in[4];
    const float* b   = (const float*)d_in[5];
    float* out = (float*)d_out;

    const int n_edges = in_sizes[2];

    zero_kernel<<<592, 256>>>();

    int warps_needed = n_edges;                       // one warp per edge
    int blocks = (warps_needed * 32 + 255) / 256;
    edge_kernel<<<blocks, 256>>>(h_s, src, dst, n_edges);

    int gblocks = (N_DST + BM - 1) / BM;              // 391
    gemm_kernel<<<gblocks, 256>>>(h_d, W, b, out);
}

// round 3
// speedup vs baseline: 1.4098x; 1.4098x over previous
#include <cuda_runtime.h>
#include <cstdint>

#define N_SRC 50000
#define N_DST 50000
#define IN_FEAT 128
#define OUT_FEAT 128

// Device-global scratch (allocation-free).
__device__ float g_neigh[(size_t)N_DST * IN_FEAT];
__device__ float g_deg[N_DST];

// ---------------------------------------------------------------------------
// Kernel 1: zero the accumulators
// ---------------------------------------------------------------------------
__global__ void zero_kernel() {
    const size_t total = (size_t)N_DST * IN_FEAT;
    size_t i = (size_t)blockIdx.x * blockDim.x + threadIdx.x;
    size_t stride = (size_t)gridDim.x * blockDim.x;
    float4* p = reinterpret_cast<float4*>(g_neigh);
    size_t n4 = total / 4;
    for (size_t j = i; j < n4; j += stride)
        p[j] = make_float4(0.f, 0.f, 0.f, 0.f);
    for (size_t j = i; j < N_DST; j += stride)
        g_deg[j] = 0.f;
}

// ---------------------------------------------------------------------------
// Kernel 2: edge aggregation. One warp per edge, vector red.add into g_neigh.
// ---------------------------------------------------------------------------
__global__ __launch_bounds__(256) void edge_kernel(
    const float* __restrict__ h_s,
    const int* __restrict__ src,
    const int* __restrict__ dst,
    int n_edges)
{
    int warp = (blockIdx.x * blockDim.x + threadIdx.x) >> 5;
    int lane = threadIdx.x & 31;
    if (warp >= n_edges) return;

    int s = __ldg(src + warp);
    int d = __ldg(dst + warp);

    const float4 v = __ldg(reinterpret_cast<const float4*>(h_s + (size_t)s * IN_FEAT) + lane);
    float* p = g_neigh + (size_t)d * IN_FEAT + lane * 4;
    asm volatile("red.global.add.v4.f32 [%0], {%1, %2, %3, %4};"
                 :: "l"(p), "f"(v.x), "f"(v.y), "f"(v.z), "f"(v.w)
                 : "memory");
    if (lane == 0) atomicAdd(g_deg + d, 1.0f);
}

// ---------------------------------------------------------------------------
// Kernel 3: fused mean + concat + Linear via TF32 mma.sync tensor cores.
//   out[d, o] = b[o] + sum_k h_d[d,k]*W[o,k] + (neigh[d,k]/max(deg,1))*W[o,128+k]
//   BM=128 rows x full N=128, BK=32, 256 threads (8 warps as 4m x 2n).
//   Each warp: 32x64 tile = 2x8 m16n8k8 tf32 MMAs per k8-step.
// ---------------------------------------------------------------------------
#define BM 128
#define BK 32
#define KPAD 36   // smem k-stride in words; bank = (4*group + tid4) -> conflict-free

__device__ __forceinline__ uint32_t f2tf32(float v) {
    uint32_t r;
    asm("cvt.rna.tf32.f32 %0, %1;" : "=r"(r) : "f"(v));
    return r;
}

__device__ __forceinline__ void mma_tf32(float c[4],
                                         uint32_t a0, uint32_t a1, uint32_t a2, uint32_t a3,
                                         uint32_t b0, uint32_t b1) {
    asm("mma.sync.aligned.m16n8k8.row.col.f32.tf32.tf32.f32 "
        "{%0,%1,%2,%3}, {%4,%5,%6,%7}, {%8,%9}, {%0,%1,%2,%3};"
        : "+f"(c[0]), "+f"(c[1]), "+f"(c[2]), "+f"(c[3])
        : "r"(a0), "r"(a1), "r"(a2), "r"(a3), "r"(b0), "r"(b1));
}

__global__ __launch_bounds__(256) void gemm_kernel(
    const float* __restrict__ h_d,
    const float* __restrict__ W,     // [128, 256] row-major
    const float* __restrict__ bias,  // [128]
    float* __restrict__ out)         // [N_DST, 128]
{
    __shared__ uint32_t As[BM][KPAD];        // [m][k] tf32
    __shared__ uint32_t Bs[OUT_FEAT][KPAD];  // [n][k] tf32
    __shared__ float sInv[BM];

    const int t    = threadIdx.x;
    const int bm   = blockIdx.x * BM;
    const int wid  = t >> 5;
    const int lane = t & 31;
    const int warp_m = wid >> 1;   // 0..3
    const int warp_n = wid & 1;    // 0..1
    const int group  = lane >> 2;  // 0..7
    const int tid4   = lane & 3;   // 0..3

    if (t < BM) {
        int r = bm + t;
        float dg = (r < N_DST) ? g_deg[r] : 1.0f;
        sInv[t] = 1.0f / fmaxf(dg, 1.0f);
    }

    float acc[2][8][4];
    #pragma unroll
    for (int mt = 0; mt < 2; ++mt)
        #pragma unroll
        for (int nt = 0; nt < 8; ++nt)
            #pragma unroll
            for (int c = 0; c < 4; ++c) acc[mt][nt][c] = 0.f;

    #pragma unroll 1
    for (int ph = 0; ph < 2; ++ph) {
        const float* __restrict__ A = ph ? g_neigh : h_d;
        #pragma unroll 1
        for (int k0 = 0; k0 < IN_FEAT; k0 += BK) {
            __syncthreads();   // prev compute done; sInv ready (iter 0)

            // --- A tile: 128 rows x 32 cols = 1024 float4 loads; 4 per thread
            #pragma unroll
            for (int i = 0; i < 4; ++i) {
                int idx = t + i * 256;          // 0..1023
                int row = idx >> 3;             // 0..127
                int c4  = (idx & 7) * 4;        // 0..28
                int gr  = bm + row;
                float4 v = make_float4(0.f, 0.f, 0.f, 0.f);
                if (gr < N_DST)
                    v = __ldg(reinterpret_cast<const float4*>(A + (size_t)gr * IN_FEAT + k0 + c4));
                float s = ph ? sInv[row] : 1.0f;
                As[row][c4 + 0] = f2tf32(v.x * s);
                As[row][c4 + 1] = f2tf32(v.y * s);
                As[row][c4 + 2] = f2tf32(v.z * s);
                As[row][c4 + 3] = f2tf32(v.w * s);
            }
            // --- B tile: Bs[o][k] = W[o][ph*128 + k0 + k]
            #pragma unroll
            for (int i = 0; i < 4; ++i) {
                int idx = t + i * 256;
                int o   = idx >> 3;
                int c4  = (idx & 7) * 4;
                float4 v = __ldg(reinterpret_cast<const float4*>(
                    W + (size_t)o * (2 * IN_FEAT) + ph * IN_FEAT + k0 + c4));
                Bs[o][c4 + 0] = f2tf32(v.x);
                Bs[o][c4 + 1] = f2tf32(v.y);
                Bs[o][c4 + 2] = f2tf32(v.z);
                Bs[o][c4 + 3] = f2tf32(v.w);
            }
            __syncthreads();

            // --- compute: 4 k8-steps
            #pragma unroll
            for (int kk = 0; kk < BK; kk += 8) {
                uint32_t af[2][4], bf[8][2];
                #pragma unroll
                for (int mt = 0; mt < 2; ++mt) {
                    int m = warp_m * 32 + mt * 16;
                    af[mt][0] = As[m + group    ][kk + tid4    ];
                    af[mt][1] = As[m + group + 8][kk + tid4    ];
                    af[mt][2] = As[m + group    ][kk + tid4 + 4];
                    af[mt][3] = As[m + group + 8][kk + tid4 + 4];
                }
                #pragma unroll
                for (int nt = 0; nt < 8; ++nt) {
                    int n = warp_n * 64 + nt * 8 + group;
                    bf[nt][0] = Bs[n][kk + tid4    ];
                    bf[nt][1] = Bs[n][kk + tid4 + 4];
                }
                #pragma unroll
                for (int mt = 0; mt < 2; ++mt)
                    #pragma unroll
                    for (int nt = 0; nt < 8; ++nt)
                        mma_tf32(acc[mt][nt], af[mt][0], af[mt][1], af[mt][2], af[mt][3],
                                 bf[nt][0], bf[nt][1]);
            }
        }
    }

    // --- epilogue: bias + store (float2 per c-pair)
    #pragma unroll
    for (int mt = 0; mt < 2; ++mt) {
        int r0 = bm + warp_m * 32 + mt * 16 + group;
        #pragma unroll
        for (int nt = 0; nt < 8; ++nt) {
            int c = warp_n * 64 + nt * 8 + tid4 * 2;
            float b0 = __ldg(bias + c);
            float b1 = __ldg(bias + c + 1);
            if (r0 < N_DST) {
                float2 v = make_float2(acc[mt][nt][0] + b0, acc[mt][nt][1] + b1);
                *reinterpret_cast<float2*>(out + (size_t)r0 * OUT_FEAT + c) = v;
            }
            int r1 = r0 + 8;
            if (r1 < N_DST) {
                float2 v = make_float2(acc[mt][nt][2] + b0, acc[mt][nt][3] + b1);
                *reinterpret_cast<float2*>(out + (size_t)r1 * OUT_FEAT + c) = v;
            }
        }
    }
}

// ---------------------------------------------------------------------------
extern "C" void kernel_launch(void* const* d_in, const int* in_sizes, int n_in,
                              void* d_out, int out_size)
{
    const float* h_s = (const float*)d_in[0];
    const float* h_d = (const float*)d_in[1];
    const int*   src = (const int*)d_in[2];
    const int*   dst = (const int*)d_in[3];
    const float* W   = (const float*)d_in[4];
    const float* b   = (const float*)d_in[5];
    float* out = (float*)d_out;

    const int n_edges = in_sizes[2];

    zero_kernel<<<1184, 256>>>();

    int blocks = (n_edges * 32 + 255) / 256;
    edge_kernel<<<blocks, 256>>>(h_s, src, dst, n_edges);

    int gblocks = (N_DST + BM - 1) / BM;              // 391
    gemm_kernel<<<gblocks, 256>>>(h_d, W, b, out);
}